// round 3
// baseline (speedup 1.0000x reference)
#include <cuda_runtime.h>

typedef unsigned long long ULL;

__device__ __forceinline__ ULL pack2(float a, float b) {
    ULL r; asm("mov.b64 %0,{%1,%2};" : "=l"(r) : "f"(a), "f"(b)); return r;
}
__device__ __forceinline__ float2 unpack2(ULL a) {
    float lo, hi; asm("mov.b64 {%0,%1},%2;" : "=f"(lo), "=f"(hi) : "l"(a));
    return make_float2(lo, hi);
}
__device__ __forceinline__ ULL ffma2(ULL a, ULL b, ULL c) {
    ULL r; asm("fma.rn.f32x2 %0,%1,%2,%3;" : "=l"(r) : "l"(a), "l"(b), "l"(c)); return r;
}
__device__ __forceinline__ ULL fmul2(ULL a, ULL b) {
    ULL r; asm("mul.rn.f32x2 %0,%1,%2;" : "=l"(r) : "l"(a), "l"(b)); return r;
}
__device__ __forceinline__ ULL fadd2(ULL a, ULL b) {
    ULL r; asm("add.rn.f32x2 %0,%1,%2;" : "=l"(r) : "l"(a), "l"(b)); return r;
}

// ---------- precomputed (window-independent) tables ----------
__device__ __align__(16) float g_Wg[9216];   // W[o][e] * gamma[e], row-major
__device__ __align__(16) float g_rsum[96];   // sum_e Wg[o][e]
__device__ __align__(16) float g_cb[96];     // sum_e W[o][e]*beta[e] + pb[o]
__device__ __align__(16) float g_BT[2160];   // bias: T[h][dy*24+dx], dy,dx in 0..14

__global__ void setup_kernel(const float* __restrict__ Wp, const float* __restrict__ Gm,
                             const float* __restrict__ Be, const float* __restrict__ Pb,
                             const float* __restrict__ Bt)
{
    const int t = threadIdx.x;   // 384 threads, 1 block
    for (int idx = t; idx < 9216; idx += 384) {
        const int e = idx % 96;
        g_Wg[idx] = Wp[idx] * Gm[e];
    }
    for (int idx = t; idx < 1350; idx += 384) {
        const int p = idx / 6, h = idx - p * 6;
        const int dy = p / 15, dx = p - dy * 15;
        g_BT[h * 360 + dy * 24 + dx] = Bt[idx];
    }
    if (t < 96) {
        float rs = 0.0f, cb = Pb[t];
        for (int e = 0; e < 96; e++) {
            const float w = Wp[t * 96 + e];
            rs += w * Gm[e];
            cb += w * Be[e];
        }
        g_rsum[t] = rs;
        g_cb[t]   = cb;
    }
}

// ---------- smem layout (floats) ----------
constexpr int OFF_K    = 0;          // 2*64*96 = 12288
constexpr int OFF_V    = 12288;      // 12288
constexpr int OFF_X    = 0;          // ALIAS after attention: 128*100 = 12800
constexpr int OFF_MS   = 24576;      // mask 128 rows * stride 68 = 8704
constexpr int OFF_BT   = 33280;      // 2160
constexpr int OFF_WG   = 35440;      // 9216
constexpr int OFF_RSUM = 44656;      // 96
constexpr int OFF_CB   = 44752;      // 96
constexpr int OFF_P1   = 44848;      // per-head LN partials: 6*128 = 768
constexpr int OFF_P2   = 45616;      // 768
constexpr int OFF_MU   = 46384;      // 128
constexpr int OFF_RS   = 46512;      // 128
constexpr int SMEM_FLOATS = 46640;   // 186560 bytes

__global__ __launch_bounds__(384, 1)
void win_attn_kernel(const float* __restrict__ Qg, const float* __restrict__ Kg,
                     const float* __restrict__ Vg, const float* __restrict__ Mg,
                     float* __restrict__ Og)
{
    extern __shared__ float sm[];
    const int t = threadIdx.x;
    const int b = blockIdx.x;              // windows 2b, 2b+1
    const int warp = t >> 5, lane = t & 31;

    // warp -> (window wi, head h); thread -> rows lane, lane+32
    const int wi = (warp >= 6) ? 1 : 0;
    const int h  = warp - wi * 6;
    const int i0 = lane;
    const int yi0 = lane >> 3, xi = lane & 7;

    // ---- q rows from gmem (early, overlaps staging) ----
    ULL q0[8], q1[8];
    {
        const float4* g0 = (const float4*)(Qg + ((size_t)(b * 2 + wi) * 64 + i0) * 96 + h * 16);
        const float4* g1 = (const float4*)(Qg + ((size_t)(b * 2 + wi) * 64 + i0 + 32) * 96 + h * 16);
        #pragma unroll
        for (int c = 0; c < 4; c++) {
            const float4 a = g0[c];
            q0[2 * c]     = pack2(a.x * 0.25f, a.y * 0.25f);
            q0[2 * c + 1] = pack2(a.z * 0.25f, a.w * 0.25f);
            const float4 d = g1[c];
            q1[2 * c]     = pack2(d.x * 0.25f, d.y * 0.25f);
            q1[2 * c + 1] = pack2(d.z * 0.25f, d.w * 0.25f);
        }
    }

    // ================= staging =================
    {
        const float4* gK = (const float4*)(Kg + (size_t)b * 12288);
        const float4* gV = (const float4*)(Vg + (size_t)b * 12288);
        float4* sK = (float4*)(sm + OFF_K);
        float4* sV = (float4*)(sm + OFF_V);
        for (int idx = t; idx < 3072; idx += 384) { sK[idx] = gK[idx]; sV[idx] = gV[idx]; }

        // mask -> stride-68 rows
        const float4* gM = (const float4*)(Mg + (size_t)b * 8192);
        float4* sM = (float4*)(sm + OFF_MS);
        for (int idx = t; idx < 2048; idx += 384) {
            const int row = idx >> 4, c = idx & 15;
            sM[row * 17 + c] = gM[idx];
        }

        float4* sW = (float4*)(sm + OFF_WG);
        const float4* gW = (const float4*)g_Wg;
        for (int idx = t; idx < 2304; idx += 384) sW[idx] = gW[idx];

        float4* sB = (float4*)(sm + OFF_BT);
        const float4* gB = (const float4*)g_BT;
        for (int idx = t; idx < 540; idx += 384) sB[idx] = gB[idx];

        if (t < 96) { sm[OFF_RSUM + t] = g_rsum[t]; sm[OFF_CB + t] = g_cb[t]; }
    }
    __syncthreads();

    // ================= attention: fused score+exp+AV =================
    const float* Kb = sm + OFF_K + wi * 6144 + h * 16;
    const float* Vb = sm + OFF_V + wi * 6144 + h * 16;
    const float4* M0 = (const float4*)(sm + OFF_MS + (wi * 64 + i0) * 68);
    const float4* M1 = (const float4*)(sm + OFF_MS + (wi * 64 + i0 + 32) * 68);
    const float* BT0 = sm + OFF_BT + h * 360 + (yi0 + 7) * 24 + (xi + 7);

    ULL acc0[8], acc1[8];
    #pragma unroll
    for (int c = 0; c < 8; c++) { acc0[c] = 0ull; acc1[c] = 0ull; }
    float sum0 = 0.0f, sum1 = 0.0f;

    #pragma unroll 4
    for (int j4 = 0; j4 < 16; j4++) {
        const float4 m0 = M0[j4], m1 = M1[j4];
        const float m0a[4] = {m0.x, m0.y, m0.z, m0.w};
        const float m1a[4] = {m1.x, m1.y, m1.z, m1.w};
        #pragma unroll
        for (int u = 0; u < 4; u++) {
            const int j  = 4 * j4 + u;
            const int yj = j >> 3, xj = j & 7;

            const ulonglong2* kp = (const ulonglong2*)(Kb + j * 96);
            const ulonglong2 ka = kp[0], kb2 = kp[1], kc = kp[2], kd = kp[3];

            ULL aA = fmul2(q0[0], ka.x);
            ULL bA = fmul2(q0[1], ka.y);
            aA = ffma2(q0[2], kb2.x, aA); bA = ffma2(q0[3], kb2.y, bA);
            aA = ffma2(q0[4], kc.x,  aA); bA = ffma2(q0[5], kc.y,  bA);
            aA = ffma2(q0[6], kd.x,  aA); bA = ffma2(q0[7], kd.y,  bA);
            const float2 fA = unpack2(fadd2(aA, bA));

            ULL aB = fmul2(q1[0], ka.x);
            ULL bB = fmul2(q1[1], ka.y);
            aB = ffma2(q1[2], kb2.x, aB); bB = ffma2(q1[3], kb2.y, bB);
            aB = ffma2(q1[4], kc.x,  aB); bB = ffma2(q1[5], kc.y,  bB);
            aB = ffma2(q1[6], kd.x,  aB); bB = ffma2(q1[7], kd.y,  bB);
            const float2 fB = unpack2(fadd2(aB, bB));

            const float bias0 = BT0[-(yj * 24 + xj)];
            const float bias1 = BT0[96 - yj * 24 - xj];

            const float s0 = fA.x + fA.y + bias0 + m0a[u];
            const float s1 = fB.x + fB.y + bias1 + m1a[u];
            const float e0 = __expf(s0);
            const float e1 = __expf(s1);
            sum0 += e0; sum1 += e1;

            const ulonglong2* vp = (const ulonglong2*)(Vb + j * 96);
            const ulonglong2 va = vp[0], vb2 = vp[1], vc = vp[2], vd = vp[3];
            const ULL p0 = pack2(e0, e0);
            const ULL p1 = pack2(e1, e1);
            acc0[0] = ffma2(p0, va.x,  acc0[0]); acc1[0] = ffma2(p1, va.x,  acc1[0]);
            acc0[1] = ffma2(p0, va.y,  acc0[1]); acc1[1] = ffma2(p1, va.y,  acc1[1]);
            acc0[2] = ffma2(p0, vb2.x, acc0[2]); acc1[2] = ffma2(p1, vb2.x, acc1[2]);
            acc0[3] = ffma2(p0, vb2.y, acc0[3]); acc1[3] = ffma2(p1, vb2.y, acc1[3]);
            acc0[4] = ffma2(p0, vc.x,  acc0[4]); acc1[4] = ffma2(p1, vc.x,  acc1[4]);
            acc0[5] = ffma2(p0, vc.y,  acc0[5]); acc1[5] = ffma2(p1, vc.y,  acc1[5]);
            acc0[6] = ffma2(p0, vd.x,  acc0[6]); acc1[6] = ffma2(p1, vd.x,  acc1[6]);
            acc0[7] = ffma2(p0, vd.y,  acc0[7]); acc1[7] = ffma2(p1, vd.y,  acc1[7]);
        }
    }

    // finalize rows: out = acc/sum + q_scaled
    const float inv0 = 1.0f / sum0;
    const float inv1 = 1.0f / sum1;
    const ULL iv0 = pack2(inv0, inv0);
    const ULL iv1 = pack2(inv1, inv1);
    ULL out0[8], out1[8];
    float p1a = 0.0f, p2a = 0.0f, p1b = 0.0f, p2b = 0.0f;
    #pragma unroll
    for (int c = 0; c < 8; c++) {
        out0[c] = ffma2(iv0, acc0[c], q0[c]);
        out1[c] = ffma2(iv1, acc1[c], q1[c]);
        const float2 fa = unpack2(out0[c]);
        const float2 fb = unpack2(out1[c]);
        p1a += fa.x + fa.y;  p2a += fa.x * fa.x + fa.y * fa.y;
        p1b += fb.x + fb.y;  p2b += fb.x * fb.x + fb.y * fb.y;
    }

    __syncthreads();   // all K/V reads done -> safe to overwrite with X

    {
        const int tok0 = wi * 64 + i0;
        ULL* xr0 = (ULL*)(sm + OFF_X + tok0 * 100 + h * 16);
        ULL* xr1 = (ULL*)(sm + OFF_X + (tok0 + 32) * 100 + h * 16);
        #pragma unroll
        for (int c = 0; c < 8; c++) { xr0[c] = out0[c]; xr1[c] = out1[c]; }
        sm[OFF_P1 + h * 128 + tok0]      = p1a;
        sm[OFF_P2 + h * 128 + tok0]      = p2a;
        sm[OFF_P1 + h * 128 + tok0 + 32] = p1b;
        sm[OFF_P2 + h * 128 + tok0 + 32] = p2b;
    }
    __syncthreads();

    // ---- LayerNorm stats: deterministic 6-way sum per token ----
    if (t < 128) {
        float s1 = 0.0f, s2 = 0.0f;
        #pragma unroll
        for (int hh = 0; hh < 6; hh++) {
            s1 += sm[OFF_P1 + hh * 128 + t];
            s2 += sm[OFF_P2 + hh * 128 + t];
        }
        const float mu  = s1 * (1.0f / 96.0f);
        const float var = s2 * (1.0f / 96.0f) - mu * mu;
        sm[OFF_MU + t] = mu;
        sm[OFF_RS + t] = rsqrtf(var + 1e-5f);
    }
    __syncthreads();

    // ================= projection with LN folded in =================
    // y[tok][o] = rs*(Wg[o]·x[tok] - mu*rsum[o]) + cb[o]
    const int og = t >> 6;                  // 0..5, 16 outputs each
    #pragma unroll
    for (int p = 0; p < 2; p++) {
        const int token = (t & 63) + p * 64;
        const float mu = sm[OFF_MU + token];
        const float rs = sm[OFF_RS + token];

        ULL x2[48];
        const float4* xr = (const float4*)(sm + OFF_X + token * 100);
        #pragma unroll
        for (int e4 = 0; e4 < 24; e4++) {
            const float4 v = xr[e4];
            x2[2 * e4]     = pack2(v.x, v.y);
            x2[2 * e4 + 1] = pack2(v.z, v.w);
        }

        float r[16];
        #pragma unroll
        for (int k = 0; k < 16; k++) {
            const int o = og * 16 + k;
            const ulonglong2* wr = (const ulonglong2*)(sm + OFF_WG + o * 96);
            ULL a  = fmul2(x2[0], wr[0].x);
            ULL bb = fmul2(x2[1], wr[0].y);
            #pragma unroll
            for (int e4 = 1; e4 < 24; e4++) {
                const ulonglong2 wv = wr[e4];
                a  = ffma2(x2[2 * e4],     wv.x, a);
                bb = ffma2(x2[2 * e4 + 1], wv.y, bb);
            }
            const float2 f = unpack2(fadd2(a, bb));
            r[k] = (f.x + f.y - mu * sm[OFF_RSUM + o]) * rs + sm[OFF_CB + o];
        }

        float4* orow = (float4*)(Og + ((size_t)b * 128 + token) * 96 + og * 16);
        #pragma unroll
        for (int k4 = 0; k4 < 4; k4++)
            orow[k4] = make_float4(r[4 * k4], r[4 * k4 + 1], r[4 * k4 + 2], r[4 * k4 + 3]);
    }
}

extern "C" void kernel_launch(void* const* d_in, const int* in_sizes, int n_in,
                              void* d_out, int out_size)
{
    const float* Q  = (const float*)d_in[0];
    const float* K  = (const float*)d_in[1];
    const float* V  = (const float*)d_in[2];
    const float* M  = (const float*)d_in[3];
    const float* Bt = (const float*)d_in[4];
    const float* Gm = (const float*)d_in[5];
    const float* Be = (const float*)d_in[6];
    const float* Wp = (const float*)d_in[7];
    const float* Pb = (const float*)d_in[8];
    float* O = (float*)d_out;

    const int nw = in_sizes[0] / (64 * 96);   // 4096 windows

    setup_kernel<<<1, 384>>>(Wp, Gm, Be, Pb, Bt);

    cudaFuncSetAttribute(win_attn_kernel,
                         cudaFuncAttributeMaxDynamicSharedMemorySize,
                         SMEM_FLOATS * (int)sizeof(float));
    win_attn_kernel<<<nw / 2, 384, SMEM_FLOATS * (int)sizeof(float)>>>(Q, K, V, M, O);
}